// round 7
// baseline (speedup 1.0000x reference)
#include <cuda_runtime.h>
#include <cuda_bf16.h>
#include <cstdint>
#include <cstddef>

// ----------------------------------------------------------------------------
// SCNN via warp-level HMMA (mma.sync bf16, fp32 accum), persistent CTAs,
// 2 CTAs/SM. M-tile = 64 rows, 256 threads/CTA. W read from gmem (L1-cached)
// instead of smem to fit the 2-CTA smem budget. Per tile:
//   sconv(FFMA) -> GEMM1(HMMA, overlap next-x load) -> GEMM2(HMMA, direct STG)
// ----------------------------------------------------------------------------

#define NB_TOTAL 50000
#define NC 45
#define ND 90
#define NT 256

#define YSTR   56   // Y row stride (bf16): 112B, conflict-free for ldmatrix
#define B1STR  56   // B1 [n=96][k=48]
#define B2STR 104   // B2 [n=48][k=96]: 208B
#define SIGSTR 104  // sig [m=64][p=96]

__device__ float g_bufA[(size_t)NB_TOTAL * 64 * NC];
__device__ float g_bufB[(size_t)NB_TOTAL * 32 * NC];
// Packed bf16 hi/lo B matrices, built once: B1=[n=96][k=48], B2=[n=48][k=96]
__device__ __nv_bfloat16 g_B1h[96 * 48], g_B1l[96 * 48];
__device__ __nv_bfloat16 g_B2h[48 * 96], g_B2l[48 * 96];

// ---------------- smem layout (bytes) ---------------------------------------
#define OFF_B1H 0
#define OFF_B1L 10752          /* +96*56*2  */
#define OFF_B2H 21504
#define OFF_B2L 31488          /* +48*104*2 */
#define OFF_YH  41472
#define OFF_YL  48640          /* +64*56*2  */
#define OFF_SGH 55808
#define OFF_SGL 69120          /* +64*104*2 */
#define OFF_X   82432
#define DYL  7168              /* OFF_YL - OFF_YH  */
#define DB1 10752
#define DSG 13312              /* OFF_SGL - OFF_SGH */
#define DB2  9984

__host__ __device__ constexpr int xstr_c(int CIN, int TB) { return TB * CIN + 4; }
__host__ __device__ constexpr int smem_total_c(int CIN, int TB) {
    return OFF_X + NC * xstr_c(CIN, TB) * 4;
}

// ---------------- PTX helpers ----------------------------------------------
__device__ __forceinline__ uint32_t smem_u32(const void* p) {
    uint32_t a;
    asm("{ .reg .u64 t; cvta.to.shared.u64 t, %1; cvt.u32.u64 %0, t; }"
        : "=r"(a) : "l"(p));
    return a;
}
__device__ __forceinline__ void ldsm_x4(uint32_t* r, uint32_t addr) {
    asm volatile("ldmatrix.sync.aligned.m8n8.x4.shared.b16 {%0,%1,%2,%3}, [%4];"
                 : "=r"(r[0]), "=r"(r[1]), "=r"(r[2]), "=r"(r[3]) : "r"(addr));
}
__device__ __forceinline__ void ldsm_x2(uint32_t* r, uint32_t addr) {
    asm volatile("ldmatrix.sync.aligned.m8n8.x2.shared.b16 {%0,%1}, [%2];"
                 : "=r"(r[0]), "=r"(r[1]) : "r"(addr));
}
__device__ __forceinline__ void mma_bf16(float* c, const uint32_t* a,
                                         uint32_t b0, uint32_t b1) {
    asm volatile(
        "mma.sync.aligned.m16n8k16.row.col.f32.bf16.bf16.f32 "
        "{%0,%1,%2,%3}, {%4,%5,%6,%7}, {%8,%9}, {%0,%1,%2,%3};"
        : "+f"(c[0]), "+f"(c[1]), "+f"(c[2]), "+f"(c[3])
        : "r"(a[0]), "r"(a[1]), "r"(a[2]), "r"(a[3]), "r"(b0), "r"(b1));
}
__device__ __forceinline__ uint32_t pack2bf(__nv_bfloat16 a, __nv_bfloat16 b) {
    return (uint32_t)__bfloat16_as_ushort(a) |
           ((uint32_t)__bfloat16_as_ushort(b) << 16);
}

// ---------------- problem constants -----------------------------------------
__host__ __device__ __forceinline__ constexpr int ggrp(int k) {
    return (k < 1) ? 0 : (k < 6) ? 1 : (k < 15) ? 2 : (k < 28) ? 3 : 4;
}
__device__ __forceinline__ float scl_of(int k) {
    const int g = ggrp(k);
    return g == 0 ? 1.77245385090552f
         : g == 1 ? 0.79266545952121f
         : g == 2 ? 0.59081795030184f
         : g == 3 ? 0.49159027f
         :          0.42988321f;
}

// ---------------- setup: pre-split B matrices to bf16 hi/lo -----------------
__global__ void build_B(const float* __restrict__ sft,
                        const float* __restrict__ isft) {
    const int tid = threadIdx.x;
    for (int i = tid; i < 96 * 48; i += NT) {      // B1[n=p(96)][k(48)]
        int n = i / 48, k = i - n * 48;
        float v = (n < ND && k < NC) ? isft[n * NC + k] : 0.f;
        __nv_bfloat16 hi = __float2bfloat16(v);
        g_B1h[i] = hi;
        g_B1l[i] = __float2bfloat16(v - __bfloat162float(hi));
    }
    for (int i = tid; i < 48 * 96; i += NT) {      // B2[n=k(48)][k=p(96)]
        int n = i / 96, p = i - n * 96;
        float v = (n < NC && p < ND) ? sft[n * ND + p] : 0.f;
        __nv_bfloat16 hi = __float2bfloat16(v);
        g_B2h[i] = hi;
        g_B2l[i] = __float2bfloat16(v - __bfloat162float(hi));
    }
}

// sconv over k in [K0,K0+KN): one thread, one row r; W read from gmem (L1-hot)
template <int K0, int KN, int CIN, int XSTR>
__device__ __forceinline__ void sconv_seg(const float* __restrict__ xb,
                                          const float* __restrict__ wb,
                                          __nv_bfloat16* __restrict__ yh,
                                          __nv_bfloat16* __restrict__ yl,
                                          int r) {
    float acc[KN];
#pragma unroll
    for (int kk = 0; kk < KN; kk++) acc[kk] = 0.f;
#pragma unroll 1
    for (int cb = 0; cb < CIN; cb += 4) {
        float wv[4][5];
#pragma unroll
        for (int cc = 0; cc < 4; cc++)
#pragma unroll
            for (int g = 0; g < 5; g++) wv[cc][g] = __ldg(wb + (cb + cc) * 5 + g);
#pragma unroll
        for (int kk = 0; kk < KN; kk++) {
            const float4 xv =
                *reinterpret_cast<const float4*>(xb + (K0 + kk) * XSTR + cb);
            const int g = ggrp(K0 + kk);
            acc[kk] = fmaf(xv.x, wv[0][g], acc[kk]);
            acc[kk] = fmaf(xv.y, wv[1][g], acc[kk]);
            acc[kk] = fmaf(xv.z, wv[2][g], acc[kk]);
            acc[kk] = fmaf(xv.w, wv[3][g], acc[kk]);
        }
    }
#pragma unroll
    for (int kk = 0; kk + 1 < KN; kk += 2) {
        const float v0 = acc[kk] * scl_of(K0 + kk);
        const float v1 = acc[kk + 1] * scl_of(K0 + kk + 1);
        const __nv_bfloat16 h0 = __float2bfloat16(v0);
        const __nv_bfloat16 h1 = __float2bfloat16(v1);
        const __nv_bfloat16 l0 = __float2bfloat16(v0 - __bfloat162float(h0));
        const __nv_bfloat16 l1 = __float2bfloat16(v1 - __bfloat162float(h1));
        *(uint32_t*)(yh + r * YSTR + K0 + kk) = pack2bf(h0, h1);
        *(uint32_t*)(yl + r * YSTR + K0 + kk) = pack2bf(l0, l1);
    }
    if constexpr (KN & 1) {
        const int k = K0 + KN - 1;
        const float v = acc[KN - 1] * scl_of(k);
        const __nv_bfloat16 h = __float2bfloat16(v);
        yh[r * YSTR + k] = h;
        yl[r * YSTR + k] = __float2bfloat16(v - __bfloat162float(h));
    }
}

// ---------------- per-layer persistent kernel (M-tile = 64 rows) ------------
template <int CIN, int COUT, int TB>
__global__ void __launch_bounds__(NT, 2)
scnn_layer(const float* __restrict__ in, const float* __restrict__ w,
           float* __restrict__ out, int ntiles) {
    static_assert(TB * COUT == 64, "MOUT must be 64");
    static_assert(CIN % 4 == 0, "c-block");
    constexpr int MIN_ = TB * CIN;
    constexpr int XSTR = xstr_c(CIN, TB);

    extern __shared__ char smc[];
    const uint32_t sb = smem_u32(smc);
    const int tid = threadIdx.x, wid = tid >> 5, lane = tid & 31;
    const int STRIDE = gridDim.x;

    __nv_bfloat16* Yh  = (__nv_bfloat16*)(smc + OFF_YH);
    __nv_bfloat16* Yl  = (__nv_bfloat16*)(smc + OFF_YL);
    __nv_bfloat16* SGh = (__nv_bfloat16*)(smc + OFF_SGH);
    __nv_bfloat16* SGl = (__nv_bfloat16*)(smc + OFF_SGL);
    float* s_x = (float*)(smc + OFF_X);

    // ---- one-time setup: zero Y region (covers k-pads), copy B tiles -------
    for (int i = tid; i < (OFF_SGH - OFF_YH) / 4; i += NT)
        ((uint32_t*)(smc + OFF_YH))[i] = 0;
    {
        const uint32_t* s1h = (const uint32_t*)g_B1h;
        const uint32_t* s1l = (const uint32_t*)g_B1l;
        uint32_t* d1h = (uint32_t*)(smc + OFF_B1H);
        uint32_t* d1l = (uint32_t*)(smc + OFF_B1L);
        for (int i = tid; i < 96 * 24; i += NT) {
            int n = i / 24, kk = i - n * 24;
            d1h[(n * B1STR) / 2 + kk] = s1h[i];
            d1l[(n * B1STR) / 2 + kk] = s1l[i];
        }
        const uint32_t* s2h = (const uint32_t*)g_B2h;
        const uint32_t* s2l = (const uint32_t*)g_B2l;
        uint32_t* d2h = (uint32_t*)(smc + OFF_B2H);
        uint32_t* d2l = (uint32_t*)(smc + OFF_B2L);
        for (int i = tid; i < 48 * 48; i += NT) {
            int n = i / 48, kk = i - n * 48;
            d2h[(n * B2STR) / 2 + kk] = s2h[i];
            d2l[(n * B2STR) / 2 + kk] = s2l[i];
        }
    }

    // ---- loop-invariant per-thread addresses (8 warps) ---------------------
    const int m0 = (wid >> 1) * 16;            // 0,16,32,48
    const int nb1 = (wid & 1) * 48;            // GEMM1 n-base
    const int nb2 = (wid & 1) * 24;            // GEMM2 n-base
    const int g = lane >> 3, rr = lane & 7;
    const uint32_t aY  = sb + OFF_YH +
        ((m0 + (g & 1) * 8 + rr) * YSTR + (g >> 1) * 8) * 2;
    const uint32_t bB1 = sb + OFF_B1H +
        ((nb1 + (g >> 1) * 8 + rr) * B1STR + (g & 1) * 8) * 2;
    const uint32_t aS  = sb + OFF_SGH +
        ((m0 + (g & 1) * 8 + rr) * SIGSTR + (g >> 1) * 8) * 2;
    const uint32_t bB2 = sb + OFF_B2H +
        ((nb2 + (g >> 1) * 8 + rr) * B2STR + (g & 1) * 8) * 2;
    const uint32_t bB2c = sb + OFF_B2H +
        ((nb2 + 16 + rr) * B2STR + (g & 1) * 8) * 2;
    const int qr = lane >> 2, qc = lane & 3;

    // sconv mapping (loop-invariant); W stays in gmem (L1-resident)
    const int rS = tid & 63;
    const int segS = tid >> 6;                 // 0..3
    const float* xbS = s_x + (rS / COUT) * CIN;
    const float* wbS = w + (rS & (COUT - 1)) * (CIN * 5);

    // ---- load first tile's x ----------------------------------------------
    int t = blockIdx.x;
    if (t < ntiles) {
        const size_t base_in = (size_t)t * (MIN_ * NC);
        for (int i = tid; i < MIN_ * NC; i += NT) {
            int m = i / NC, k = i - m * NC;
            s_x[k * XSTR + m] = in[base_in + i];
        }
    }
    __syncthreads();

    // ---- persistent tile loop ----------------------------------------------
    for (; t < ntiles;) {
        const int tn = t + STRIDE;

        // phase A: sconv -> Y (bf16 hi/lo)
        if      (segS == 0) sconv_seg< 0, 12, CIN, XSTR>(xbS, wbS, Yh, Yl, rS);
        else if (segS == 1) sconv_seg<12, 12, CIN, XSTR>(xbS, wbS, Yh, Yl, rS);
        else if (segS == 2) sconv_seg<24, 12, CIN, XSTR>(xbS, wbS, Yh, Yl, rS);
        else                sconv_seg<36,  9, CIN, XSTR>(xbS, wbS, Yh, Yl, rS);
        __syncthreads();

        // phase B: GEMM1 sig = relu(Y * B1^T)  [+ overlap next x load]
        {
            float c[6][4];
#pragma unroll
            for (int i = 0; i < 6; i++)
#pragma unroll
                for (int j = 0; j < 4; j++) c[i][j] = 0.f;

#pragma unroll
            for (int ks = 0; ks < 3; ks++) {
                const uint32_t ao = aY + ks * 32;
                uint32_t ah[4], al[4];
                ldsm_x4(ah, ao);
                ldsm_x4(al, ao + DYL);
#pragma unroll
                for (int ntp = 0; ntp < 3; ntp++) {
                    const uint32_t bo = bB1 + ks * 32 + ntp * (16 * B1STR * 2);
                    uint32_t bh[4], bl[4];
                    ldsm_x4(bh, bo);
                    ldsm_x4(bl, bo + DB1);
                    mma_bf16(c[2 * ntp], ah, bh[0], bh[1]);
                    mma_bf16(c[2 * ntp], ah, bl[0], bl[1]);
                    mma_bf16(c[2 * ntp], al, bh[0], bh[1]);
                    mma_bf16(c[2 * ntp + 1], ah, bh[2], bh[3]);
                    mma_bf16(c[2 * ntp + 1], ah, bl[2], bl[3]);
                    mma_bf16(c[2 * ntp + 1], al, bh[2], bh[3]);
                }
            }
            // overlap: load next tile's x (x dead; Y/SIG untouched)
            if (tn < ntiles) {
                const size_t base_in = (size_t)tn * (MIN_ * NC);
                for (int i = tid; i < MIN_ * NC; i += NT) {
                    int m = i / NC, k = i - m * NC;
                    s_x[k * XSTR + m] = in[base_in + i];
                }
            }
            // epilogue: relu, hi/lo split, packed stores to sig
#pragma unroll
            for (int nt = 0; nt < 6; nt++) {
                const int col = nb1 + nt * 8 + 2 * qc;
#pragma unroll
                for (int half = 0; half < 2; half++) {
                    const int row = m0 + qr + 8 * half;
                    const float v0 = fmaxf(c[nt][2 * half], 0.f);
                    const float v1 = fmaxf(c[nt][2 * half + 1], 0.f);
                    const __nv_bfloat16 h0 = __float2bfloat16(v0);
                    const __nv_bfloat16 h1 = __float2bfloat16(v1);
                    const __nv_bfloat16 l0 =
                        __float2bfloat16(v0 - __bfloat162float(h0));
                    const __nv_bfloat16 l1 =
                        __float2bfloat16(v1 - __bfloat162float(h1));
                    *(uint32_t*)(SGh + row * SIGSTR + col) = pack2bf(h0, h1);
                    *(uint32_t*)(SGl + row * SIGSTR + col) = pack2bf(l0, l1);
                }
            }
        }
        __syncthreads();

        // phase C: GEMM2 out = sig * B2^T, fragments stored straight to gmem
        {
            float c[3][4];
#pragma unroll
            for (int i = 0; i < 3; i++)
#pragma unroll
                for (int j = 0; j < 4; j++) c[i][j] = 0.f;

#pragma unroll
            for (int ks = 0; ks < 6; ks++) {
                const uint32_t ao = aS + ks * 32;
                uint32_t ah[4], al[4];
                ldsm_x4(ah, ao);
                ldsm_x4(al, ao + DSG);
                {
                    const uint32_t bo = bB2 + ks * 32;
                    uint32_t bh[4], bl[4];
                    ldsm_x4(bh, bo);
                    ldsm_x4(bl, bo + DB2);
                    mma_bf16(c[0], ah, bh[0], bh[1]);
                    mma_bf16(c[0], ah, bl[0], bl[1]);
                    mma_bf16(c[0], al, bh[0], bh[1]);
                    mma_bf16(c[1], ah, bh[2], bh[3]);
                    mma_bf16(c[1], ah, bl[2], bl[3]);
                    mma_bf16(c[1], al, bh[2], bh[3]);
                }
                {
                    const uint32_t bo = bB2c + ks * 32;
                    uint32_t bh[2], bl[2];
                    ldsm_x2(bh, bo);
                    ldsm_x2(bl, bo + DB2);
                    mma_bf16(c[2], ah, bh[0], bh[1]);
                    mma_bf16(c[2], ah, bl[0], bl[1]);
                    mma_bf16(c[2], al, bh[0], bh[1]);
                }
            }
            // direct guarded stores
            const size_t base_out = (size_t)t * (64 * NC);
#pragma unroll
            for (int nt = 0; nt < 3; nt++) {
                const int col = nb2 + nt * 8 + 2 * qc;
#pragma unroll
                for (int half = 0; half < 2; half++) {
                    const int row = m0 + qr + 8 * half;
                    const size_t idx = base_out + (size_t)row * NC + col;
                    if (col < NC)     out[idx]     = c[nt][2 * half];
                    if (col + 1 < NC) out[idx + 1] = c[nt][2 * half + 1];
                }
            }
        }
        __syncthreads();
        t = tn;
    }
}

// ---------------- host ------------------------------------------------------
extern "C" void kernel_launch(void* const* d_in, const int* in_sizes, int n_in,
                              void* d_out, int out_size) {
    (void)in_sizes; (void)n_in; (void)out_size;

    const float* x    = (const float*)d_in[0];
    const float* sft  = (const float*)d_in[1];
    const float* isft = (const float*)d_in[2];
    const float* w1   = (const float*)d_in[3];
    const float* w2   = (const float*)d_in[4];
    const float* w3   = (const float*)d_in[5];
    const float* w4   = (const float*)d_in[6];
    const float* w5   = (const float*)d_in[7];
    const float* w6   = (const float*)d_in[8];
    float* out = (float*)d_out;

    float *bufA = nullptr, *bufB = nullptr;
    cudaGetSymbolAddress((void**)&bufA, g_bufA);
    cudaGetSymbolAddress((void**)&bufB, g_bufB);

    cudaFuncSetAttribute((const void*)scnn_layer<4, 16, 4>,
        cudaFuncAttributeMaxDynamicSharedMemorySize, smem_total_c(4, 4));
    cudaFuncSetAttribute((const void*)scnn_layer<16, 32, 2>,
        cudaFuncAttributeMaxDynamicSharedMemorySize, smem_total_c(16, 2));
    cudaFuncSetAttribute((const void*)scnn_layer<32, 64, 1>,
        cudaFuncAttributeMaxDynamicSharedMemorySize, smem_total_c(32, 1));
    cudaFuncSetAttribute((const void*)scnn_layer<64, 32, 2>,
        cudaFuncAttributeMaxDynamicSharedMemorySize, smem_total_c(64, 2));
    cudaFuncSetAttribute((const void*)scnn_layer<32, 16, 4>,
        cudaFuncAttributeMaxDynamicSharedMemorySize, smem_total_c(32, 4));
    cudaFuncSetAttribute((const void*)scnn_layer<16, 4, 16>,
        cudaFuncAttributeMaxDynamicSharedMemorySize, smem_total_c(16, 16));

    build_B<<<1, NT>>>(sft, isft);

    const int GRID2 = 296;   // 2 CTAs/SM * 148 SMs
    scnn_layer<4, 16, 4><<<GRID2, NT, smem_total_c(4, 4)>>>(
        x, w1, bufA, NB_TOTAL / 4);
    scnn_layer<16, 32, 2><<<GRID2, NT, smem_total_c(16, 2)>>>(
        bufA, w2, bufB, NB_TOTAL / 2);
    scnn_layer<32, 64, 1><<<GRID2, NT, smem_total_c(32, 1)>>>(
        bufB, w3, bufA, NB_TOTAL);
    scnn_layer<64, 32, 2><<<GRID2, NT, smem_total_c(64, 2)>>>(
        bufA, w4, bufB, NB_TOTAL / 2);
    scnn_layer<32, 16, 4><<<GRID2, NT, smem_total_c(32, 4)>>>(
        bufB, w5, bufA, NB_TOTAL / 4);
    scnn_layer<16, 4, 16><<<GRID2, NT, smem_total_c(16, 16)>>>(
        bufA, w6, out, NB_TOTAL / 16);
}

// round 8
// speedup vs baseline: 3.4655x; 3.4655x over previous
#include <cuda_runtime.h>
#include <cuda_bf16.h>
#include <cstdint>
#include <cstddef>

// ----------------------------------------------------------------------------
// SCNN via warp-level HMMA (mma.sync bf16, fp32 accum), persistent CTAs.
// R8: register-fused GEMM1->GEMM2 (no sig smem), inter-layer buffers in
// [k][batch][ch] layout so sconv reads x from gmem as broadcast float4.
// Each warp owns m16 x full-N; 16 warps (M=256) for L1-L3, 8 warps (M=128,
// 2 CTAs/SM) for L4-L6. W stays in smem (conflict-free broadcast).
// ----------------------------------------------------------------------------

#define NB_TOTAL 50000
#define NC 45
#define ND 90
#define YSTR   56    // Y row stride (bf16): 112B, conflict-free ldmatrix
#define B1STR  56    // B1 [n=96][k=48]
#define B2STR 104    // B2 [n=48][k=96]: 208B, conflict-free

__device__ float g_bufA[(size_t)NB_TOTAL * 64 * NC];
__device__ float g_bufB[(size_t)NB_TOTAL * 32 * NC];
__device__ __nv_bfloat16 g_B1h[96 * 48], g_B1l[96 * 48];
__device__ __nv_bfloat16 g_B2h[48 * 96], g_B2l[48 * 96];

// ---------------- smem layout (bytes) ---------------------------------------
#define OFF_B1H 0
#define OFF_B1L 10752
#define OFF_B2H 21504
#define OFF_B2L 31488
#define OFF_YH  41472          /* Yh then Yl; then optional X; then W */
#define DB1 10752
#define DB2  9984

__host__ __device__ constexpr int smem_total_c(int CIN, int COUT, int TB,
                                               int NW, int MODE_IN) {
    return OFF_YH + 2 * (NW * 16 * YSTR * 2) +
           (MODE_IN == 0 ? NC * (TB * CIN + 4) * 4 : 0) +
           COUT * (CIN * 5 + 1) * 4;
}

// ---------------- PTX helpers ----------------------------------------------
__device__ __forceinline__ uint32_t smem_u32(const void* p) {
    uint32_t a;
    asm("{ .reg .u64 t; cvta.to.shared.u64 t, %1; cvt.u32.u64 %0, t; }"
        : "=r"(a) : "l"(p));
    return a;
}
__device__ __forceinline__ void ldsm_x4(uint32_t* r, uint32_t addr) {
    asm volatile("ldmatrix.sync.aligned.m8n8.x4.shared.b16 {%0,%1,%2,%3}, [%4];"
                 : "=r"(r[0]), "=r"(r[1]), "=r"(r[2]), "=r"(r[3]) : "r"(addr));
}
__device__ __forceinline__ void mma_bf16(float* c, const uint32_t* a,
                                         uint32_t b0, uint32_t b1) {
    asm volatile(
        "mma.sync.aligned.m16n8k16.row.col.f32.bf16.bf16.f32 "
        "{%0,%1,%2,%3}, {%4,%5,%6,%7}, {%8,%9}, {%0,%1,%2,%3};"
        : "+f"(c[0]), "+f"(c[1]), "+f"(c[2]), "+f"(c[3])
        : "r"(a[0]), "r"(a[1]), "r"(a[2]), "r"(a[3]), "r"(b0), "r"(b1));
}
__device__ __forceinline__ uint32_t pack2bf(__nv_bfloat16 a, __nv_bfloat16 b) {
    return (uint32_t)__bfloat16_as_ushort(a) |
           ((uint32_t)__bfloat16_as_ushort(b) << 16);
}

// ---------------- problem constants -----------------------------------------
__host__ __device__ __forceinline__ constexpr int ggrp(int k) {
    return (k < 1) ? 0 : (k < 6) ? 1 : (k < 15) ? 2 : (k < 28) ? 3 : 4;
}
__device__ __forceinline__ float scl_of(int k) {
    const int g = ggrp(k);
    return g == 0 ? 1.77245385090552f
         : g == 1 ? 0.79266545952121f
         : g == 2 ? 0.59081795030184f
         : g == 3 ? 0.49159027f
         :          0.42988321f;
}

// ---------------- setup: pre-split B matrices to bf16 hi/lo -----------------
__global__ void build_B(const float* __restrict__ sft,
                        const float* __restrict__ isft) {
    const int tid = threadIdx.x;
    for (int i = tid; i < 96 * 48; i += 256) {     // B1[n=p(96)][k(48)]
        int n = i / 48, k = i - n * 48;
        float v = (n < ND && k < NC) ? isft[n * NC + k] : 0.f;
        __nv_bfloat16 hi = __float2bfloat16(v);
        g_B1h[i] = hi;
        g_B1l[i] = __float2bfloat16(v - __bfloat162float(hi));
    }
    for (int i = tid; i < 48 * 96; i += 256) {     // B2[n=k(48)][k=p(96)]
        int n = i / 96, p = i - n * 96;
        float v = (n < NC && p < ND) ? sft[n * ND + p] : 0.f;
        __nv_bfloat16 hi = __float2bfloat16(v);
        g_B2h[i] = hi;
        g_B2l[i] = __float2bfloat16(v - __bfloat162float(hi));
    }
}

// sconv over k in [K0,K0+KN): one thread, one row r; bf16 hi/lo pairs to Y.
// MODE_IN==0: x from smem [k][m] (XSTR). MODE_IN==1: x from gmem [k][b][c].
template <int K0, int KN, int CIN, int XSTR, int MODE_IN>
__device__ __forceinline__ void sconv_seg(const float* __restrict__ xb,
                                          const float* __restrict__ wb,
                                          __nv_bfloat16* __restrict__ yh,
                                          __nv_bfloat16* __restrict__ yl,
                                          int r) {
    constexpr size_t KS = (size_t)NB_TOTAL * CIN;  // gmem k-stride (elems)
    float acc[KN];
#pragma unroll
    for (int kk = 0; kk < KN; kk++) acc[kk] = 0.f;
#pragma unroll 1
    for (int cb = 0; cb < CIN; cb += 4) {
        float wv[4][5];
#pragma unroll
        for (int cc = 0; cc < 4; cc++)
#pragma unroll
            for (int g = 0; g < 5; g++) wv[cc][g] = wb[(cb + cc) * 5 + g];
#pragma unroll
        for (int kk = 0; kk < KN; kk++) {
            float4 xv;
            if constexpr (MODE_IN == 0)
                xv = *reinterpret_cast<const float4*>(xb + (K0 + kk) * XSTR + cb);
            else
                xv = __ldg(reinterpret_cast<const float4*>(
                        xb + (size_t)(K0 + kk) * KS + cb));
            const int g = ggrp(K0 + kk);
            acc[kk] = fmaf(xv.x, wv[0][g], acc[kk]);
            acc[kk] = fmaf(xv.y, wv[1][g], acc[kk]);
            acc[kk] = fmaf(xv.z, wv[2][g], acc[kk]);
            acc[kk] = fmaf(xv.w, wv[3][g], acc[kk]);
        }
    }
#pragma unroll
    for (int kk = 0; kk + 1 < KN; kk += 2) {       // K0 even -> 4B aligned
        const float v0 = acc[kk] * scl_of(K0 + kk);
        const float v1 = acc[kk + 1] * scl_of(K0 + kk + 1);
        const __nv_bfloat16 h0 = __float2bfloat16(v0);
        const __nv_bfloat16 h1 = __float2bfloat16(v1);
        *(uint32_t*)(yh + r * YSTR + K0 + kk) = pack2bf(h0, h1);
        *(uint32_t*)(yl + r * YSTR + K0 + kk) =
            pack2bf(__float2bfloat16(v0 - __bfloat162float(h0)),
                    __float2bfloat16(v1 - __bfloat162float(h1)));
    }
    if constexpr (KN & 1) {
        const int k = K0 + KN - 1;
        const float v = acc[KN - 1] * scl_of(k);
        const __nv_bfloat16 h = __float2bfloat16(v);
        yh[r * YSTR + k] = h;
        yl[r * YSTR + k] = __float2bfloat16(v - __bfloat162float(h));
    }
}

// ---------------- per-layer persistent kernel -------------------------------
template <int CIN, int COUT, int TB, int NW, int MODE_IN, int MODE_OUT>
__global__ void __launch_bounds__(NW * 32, NW == 8 ? 2 : 1)
scnn_layer(const float* __restrict__ in, const float* __restrict__ w,
           float* __restrict__ out, int ntiles) {
    constexpr int M    = NW * 16;
    constexpr int NTT  = NW * 32;
    constexpr int MIN_ = TB * CIN;
    constexpr int XSTR = MIN_ + 4;
    constexpr int WSTR = CIN * 5 + 1;
    constexpr int YSZ  = M * YSTR * 2;
    constexpr int OFF_YL_ = OFF_YH + YSZ;
    constexpr int OFF_X_  = OFF_YH + 2 * YSZ;
    constexpr int XSZ  = (MODE_IN == 0) ? NC * XSTR * 4 : 0;
    constexpr int OFF_W_  = OFF_X_ + XSZ;
    constexpr int MSHIFT  = (NW == 16) ? 8 : 7;
    static_assert(TB * COUT == M, "tile");
    static_assert(CIN % 4 == 0, "c-block");

    extern __shared__ char smc[];
    const uint32_t sb = smem_u32(smc);
    const int tid = threadIdx.x, wid = tid >> 5, lane = tid & 31;

    __nv_bfloat16* Yh = (__nv_bfloat16*)(smc + OFF_YH);
    __nv_bfloat16* Yl = (__nv_bfloat16*)(smc + OFF_YL_);
    float* s_x = (float*)(smc + OFF_X_);
    float* s_w = (float*)(smc + OFF_W_);

    // ---- one-time setup: zero Y (pads), copy B tiles, load W ---------------
    for (int i = tid; i < 2 * YSZ / 4; i += NTT)
        ((uint32_t*)(smc + OFF_YH))[i] = 0;
    {
        const uint32_t* s1h = (const uint32_t*)g_B1h;
        const uint32_t* s1l = (const uint32_t*)g_B1l;
        uint32_t* d1h = (uint32_t*)(smc + OFF_B1H);
        uint32_t* d1l = (uint32_t*)(smc + OFF_B1L);
        for (int i = tid; i < 96 * 24; i += NTT) {
            int n = i / 24, kk = i - n * 24;
            d1h[(n * B1STR) / 2 + kk] = s1h[i];
            d1l[(n * B1STR) / 2 + kk] = s1l[i];
        }
        const uint32_t* s2h = (const uint32_t*)g_B2h;
        const uint32_t* s2l = (const uint32_t*)g_B2l;
        uint32_t* d2h = (uint32_t*)(smc + OFF_B2H);
        uint32_t* d2l = (uint32_t*)(smc + OFF_B2L);
        for (int i = tid; i < 48 * 48; i += NTT) {
            int n = i / 48, kk = i - n * 48;
            d2h[(n * B2STR) / 2 + kk] = s2h[i];
            d2l[(n * B2STR) / 2 + kk] = s2l[i];
        }
    }
    for (int i = tid; i < COUT * CIN * 5; i += NTT) {
        int o = i / (CIN * 5);
        s_w[o * WSTR + (i - o * (CIN * 5))] = w[i];
    }

    // ---- loop-invariant addresses ------------------------------------------
    const int m0 = wid * 16;
    const int g = lane >> 3, rr = lane & 7;
    const uint32_t aY  = sb + OFF_YH +
        ((m0 + (g & 1) * 8 + rr) * YSTR + (g >> 1) * 8) * 2;
    const uint32_t bB1 = sb + OFF_B1H +
        (((g >> 1) * 8 + rr) * B1STR + (g & 1) * 8) * 2;
    const uint32_t bB2 = sb + OFF_B2H +
        (((g >> 1) * 8 + rr) * B2STR + (g & 1) * 8) * 2;
    const int qr = lane >> 2, qc = lane & 3;

    // sconv mapping
    const int rS = tid & (M - 1);
    const int segS = tid >> MSHIFT;            // 0 or 1 (warp-uniform)
    const int tS = rS / COUT, oS = rS % COUT;
    const float* wbS = s_w + oS * WSTR;

    // ---- L1 only: stage first tile's x -------------------------------------
    int t = blockIdx.x;
    if constexpr (MODE_IN == 0) {
        if (t < ntiles) {
            const size_t bi = (size_t)t * (MIN_ * NC);
            for (int i = tid; i < MIN_ * NC; i += NTT) {
                int m = i / NC, k = i - m * NC;
                s_x[k * XSTR + m] = in[bi + i];
            }
        }
    }
    __syncthreads();

    // ---- persistent tile loop ----------------------------------------------
    for (; t < ntiles; t += gridDim.x) {
        // phase A: sconv -> Y
        {
            const float* xb;
            if constexpr (MODE_IN == 0) {
                xb = s_x + tS * CIN;
            } else {
                int b = t * TB + tS;
                if (b >= NB_TOTAL) b = NB_TOTAL - 1;   // clamp (guarded store)
                xb = in + (size_t)b * CIN;
            }
            if (segS == 0)
                sconv_seg< 0, 22, CIN, XSTR, MODE_IN>(xb, wbS, Yh, Yl, rS);
            else
                sconv_seg<22, 23, CIN, XSTR, MODE_IN>(xb, wbS, Yh, Yl, rS);
        }
        __syncthreads();

        // phase B: GEMM1 (full N=96 per warp) -> register relu/split -> GEMM2
        float c1[12][4];
#pragma unroll
        for (int i = 0; i < 12; i++)
#pragma unroll
            for (int j = 0; j < 4; j++) c1[i][j] = 0.f;

#pragma unroll
        for (int ks = 0; ks < 3; ks++) {
            uint32_t ah[4], al[4];
            ldsm_x4(ah, aY + ks * 32);
            ldsm_x4(al, aY + ks * 32 + YSZ);
#pragma unroll
            for (int np = 0; np < 6; np++) {
                const uint32_t bo = bB1 + ks * 32 + np * (16 * B1STR * 2);
                uint32_t bh[4], bl[4];
                ldsm_x4(bh, bo);
                ldsm_x4(bl, bo + DB1);
                mma_bf16(c1[2 * np], ah, bh[0], bh[1]);
                mma_bf16(c1[2 * np], ah, bl[0], bl[1]);
                mma_bf16(c1[2 * np], al, bh[0], bh[1]);
                mma_bf16(c1[2 * np + 1], ah, bh[2], bh[3]);
                mma_bf16(c1[2 * np + 1], ah, bl[2], bl[3]);
                mma_bf16(c1[2 * np + 1], al, bh[2], bh[3]);
            }
        }

        // L1 only: overlap next tile's x staging (x dead after sconv)
        if constexpr (MODE_IN == 0) {
            const int tn = t + gridDim.x;
            if (tn < ntiles) {
                const size_t bi = (size_t)tn * (MIN_ * NC);
                for (int i = tid; i < MIN_ * NC; i += NTT) {
                    int m = i / NC, k = i - m * NC;
                    s_x[k * XSTR + m] = in[bi + i];
                }
            }
        }

        float c2[6][4];
#pragma unroll
        for (int i = 0; i < 6; i++)
#pragma unroll
            for (int j = 0; j < 4; j++) c2[i][j] = 0.f;

#pragma unroll
        for (int kc = 0; kc < 6; kc++) {
            // repack: sig fragment (relu + hi/lo split) from c1, in registers
            uint32_t a2h[4], a2l[4];
#pragma unroll
            for (int u = 0; u < 2; u++)
#pragma unroll
                for (int v = 0; v < 2; v++) {
                    const float p0 = fmaxf(c1[2 * kc + u][2 * v], 0.f);
                    const float p1 = fmaxf(c1[2 * kc + u][2 * v + 1], 0.f);
                    const __nv_bfloat16 h0 = __float2bfloat16(p0);
                    const __nv_bfloat16 h1 = __float2bfloat16(p1);
                    a2h[2 * u + v] = pack2bf(h0, h1);
                    a2l[2 * u + v] =
                        pack2bf(__float2bfloat16(p0 - __bfloat162float(h0)),
                                __float2bfloat16(p1 - __bfloat162float(h1)));
                }
#pragma unroll
            for (int np = 0; np < 3; np++) {
                const uint32_t bo = bB2 + kc * 32 + np * (16 * B2STR * 2);
                uint32_t bh[4], bl[4];
                ldsm_x4(bh, bo);
                ldsm_x4(bl, bo + DB2);
                mma_bf16(c2[2 * np], a2h, bh[0], bh[1]);
                mma_bf16(c2[2 * np], a2h, bl[0], bl[1]);
                mma_bf16(c2[2 * np], a2l, bh[0], bh[1]);
                mma_bf16(c2[2 * np + 1], a2h, bh[2], bh[3]);
                mma_bf16(c2[2 * np + 1], a2h, bl[2], bl[3]);
                mma_bf16(c2[2 * np + 1], a2l, bh[2], bh[3]);
            }
        }

        // store c2 straight to gmem
        if constexpr (MODE_OUT == 1) {           // [k][b][ch] layout
            const int tb0 = t * TB;
#pragma unroll
            for (int j2 = 0; j2 < 6; j2++) {
                const int col0 = j2 * 8 + 2 * qc;
#pragma unroll
                for (int half = 0; half < 2; half++) {
                    const int m = m0 + qr + 8 * half;
                    const int b = tb0 + m / COUT;
                    const int ch = m % COUT;
                    if (b < NB_TOTAL) {
                        if (col0 < NC)
                            out[((size_t)col0 * NB_TOTAL + b) * COUT + ch] =
                                c2[j2][2 * half];
                        if (col0 + 1 < NC)
                            out[((size_t)(col0 + 1) * NB_TOTAL + b) * COUT + ch] =
                                c2[j2][2 * half + 1];
                    }
                }
            }
        } else {                                 // standard [b][ch][k] (L6)
#pragma unroll
            for (int j2 = 0; j2 < 6; j2++) {
                const int col0 = j2 * 8 + 2 * qc;
#pragma unroll
                for (int half = 0; half < 2; half++) {
                    const int m = m0 + qr + 8 * half;
                    if (t * TB + m / COUT < NB_TOTAL) {
                        const size_t ro = ((size_t)t * M + m) * NC;
                        if (col0 < NC)     out[ro + col0]     = c2[j2][2 * half];
                        if (col0 + 1 < NC) out[ro + col0 + 1] = c2[j2][2 * half + 1];
                    }
                }
            }
        }
        __syncthreads();   // protect Y (and L1's s_x) before next sconv
    }
}

// ---------------- host ------------------------------------------------------
extern "C" void kernel_launch(void* const* d_in, const int* in_sizes, int n_in,
                              void* d_out, int out_size) {
    (void)in_sizes; (void)n_in; (void)out_size;

    const float* x    = (const float*)d_in[0];
    const float* sft  = (const float*)d_in[1];
    const float* isft = (const float*)d_in[2];
    const float* w1   = (const float*)d_in[3];
    const float* w2   = (const float*)d_in[4];
    const float* w3   = (const float*)d_in[5];
    const float* w4   = (const float*)d_in[6];
    const float* w5   = (const float*)d_in[7];
    const float* w6   = (const float*)d_in[8];
    float* out = (float*)d_out;

    float *bufA = nullptr, *bufB = nullptr;
    cudaGetSymbolAddress((void**)&bufA, g_bufA);
    cudaGetSymbolAddress((void**)&bufB, g_bufB);

    cudaFuncSetAttribute((const void*)scnn_layer<4, 16, 16, 16, 0, 1>,
        cudaFuncAttributeMaxDynamicSharedMemorySize, smem_total_c(4, 16, 16, 16, 0));
    cudaFuncSetAttribute((const void*)scnn_layer<16, 32, 8, 16, 1, 1>,
        cudaFuncAttributeMaxDynamicSharedMemorySize, smem_total_c(16, 32, 8, 16, 1));
    cudaFuncSetAttribute((const void*)scnn_layer<32, 64, 4, 16, 1, 1>,
        cudaFuncAttributeMaxDynamicSharedMemorySize, smem_total_c(32, 64, 4, 16, 1));
    cudaFuncSetAttribute((const void*)scnn_layer<64, 32, 4, 8, 1, 1>,
        cudaFuncAttributeMaxDynamicSharedMemorySize, smem_total_c(64, 32, 4, 8, 1));
    cudaFuncSetAttribute((const void*)scnn_layer<32, 16, 8, 8, 1, 1>,
        cudaFuncAttributeMaxDynamicSharedMemorySize, smem_total_c(32, 16, 8, 8, 1));
    cudaFuncSetAttribute((const void*)scnn_layer<16, 4, 32, 8, 1, 0>,
        cudaFuncAttributeMaxDynamicSharedMemorySize, smem_total_c(16, 4, 32, 8, 0) -
            NC * (32 * 16 + 4) * 4);   // MODE_IN=1: no X region

    build_B<<<1, 256>>>(sft, isft);

    // L1: in [b][c][k] via smem stage; out kbc. M=256, 16 warps.
    scnn_layer<4, 16, 16, 16, 0, 1><<<148, 512,
        smem_total_c(4, 16, 16, 16, 0)>>>(x, w1, bufA, 3125);
    // L2-L5: kbc -> kbc
    scnn_layer<16, 32, 8, 16, 1, 1><<<148, 512,
        smem_total_c(16, 32, 8, 16, 1)>>>(bufA, w2, bufB, 6250);
    scnn_layer<32, 64, 4, 16, 1, 1><<<148, 512,
        smem_total_c(32, 64, 4, 16, 1)>>>(bufB, w3, bufA, 12500);
    scnn_layer<64, 32, 4, 8, 1, 1><<<296, 256,
        smem_total_c(64, 32, 4, 8, 1)>>>(bufA, w4, bufB, 12500);
    scnn_layer<32, 16, 8, 8, 1, 1><<<296, 256,
        smem_total_c(32, 16, 8, 8, 1)>>>(bufB, w5, bufA, 6250);
    // L6: kbc -> standard [b][ch][k] into d_out (tail tile guarded)
    scnn_layer<16, 4, 32, 8, 1, 0><<<296, 256,
        smem_total_c(16, 4, 32, 8, 1)>>>(bufA, w6, out, 1563);
}

// round 9
// speedup vs baseline: 3.4721x; 1.0019x over previous
#include <cuda_runtime.h>
#include <cuda_bf16.h>
#include <cstdint>
#include <cstddef>

// ----------------------------------------------------------------------------
// SCNN via warp-level HMMA (mma.sync bf16, fp32 accum), persistent CTAs.
// R8: register-fused GEMM1->GEMM2 (no sig smem), inter-layer buffers in
// [k][batch][ch] layout so sconv reads x from gmem as broadcast float4.
// Each warp owns m16 x full-N; 16 warps (M=256) for L1-L3, 8 warps (M=128,
// 2 CTAs/SM) for L4-L6. W stays in smem (conflict-free broadcast).
// ----------------------------------------------------------------------------

#define NB_TOTAL 50000
#define NC 45
#define ND 90
#define YSTR   56    // Y row stride (bf16): 112B, conflict-free ldmatrix
#define B1STR  56    // B1 [n=96][k=48]
#define B2STR 104    // B2 [n=48][k=96]: 208B, conflict-free

__device__ float g_bufA[(size_t)NB_TOTAL * 64 * NC];
__device__ float g_bufB[(size_t)NB_TOTAL * 32 * NC];
__device__ __nv_bfloat16 g_B1h[96 * 48], g_B1l[96 * 48];
__device__ __nv_bfloat16 g_B2h[48 * 96], g_B2l[48 * 96];

// ---------------- smem layout (bytes) ---------------------------------------
#define OFF_B1H 0
#define OFF_B1L 10752
#define OFF_B2H 21504
#define OFF_B2L 31488
#define OFF_YH  41472          /* Yh then Yl; then optional X; then W */
#define DB1 10752
#define DB2  9984

__host__ __device__ constexpr int smem_total_c(int CIN, int COUT, int TB,
                                               int NW, int MODE_IN) {
    return OFF_YH + 2 * (NW * 16 * YSTR * 2) +
           (MODE_IN == 0 ? NC * (TB * CIN + 4) * 4 : 0) +
           COUT * (CIN * 5 + 1) * 4;
}

// ---------------- PTX helpers ----------------------------------------------
__device__ __forceinline__ uint32_t smem_u32(const void* p) {
    uint32_t a;
    asm("{ .reg .u64 t; cvta.to.shared.u64 t, %1; cvt.u32.u64 %0, t; }"
        : "=r"(a) : "l"(p));
    return a;
}
__device__ __forceinline__ void ldsm_x4(uint32_t* r, uint32_t addr) {
    asm volatile("ldmatrix.sync.aligned.m8n8.x4.shared.b16 {%0,%1,%2,%3}, [%4];"
                 : "=r"(r[0]), "=r"(r[1]), "=r"(r[2]), "=r"(r[3]) : "r"(addr));
}
__device__ __forceinline__ void mma_bf16(float* c, const uint32_t* a,
                                         uint32_t b0, uint32_t b1) {
    asm volatile(
        "mma.sync.aligned.m16n8k16.row.col.f32.bf16.bf16.f32 "
        "{%0,%1,%2,%3}, {%4,%5,%6,%7}, {%8,%9}, {%0,%1,%2,%3};"
        : "+f"(c[0]), "+f"(c[1]), "+f"(c[2]), "+f"(c[3])
        : "r"(a[0]), "r"(a[1]), "r"(a[2]), "r"(a[3]), "r"(b0), "r"(b1));
}
__device__ __forceinline__ uint32_t pack2bf(__nv_bfloat16 a, __nv_bfloat16 b) {
    return (uint32_t)__bfloat16_as_ushort(a) |
           ((uint32_t)__bfloat16_as_ushort(b) << 16);
}

// ---------------- problem constants -----------------------------------------
__host__ __device__ __forceinline__ constexpr int ggrp(int k) {
    return (k < 1) ? 0 : (k < 6) ? 1 : (k < 15) ? 2 : (k < 28) ? 3 : 4;
}
__device__ __forceinline__ float scl_of(int k) {
    const int g = ggrp(k);
    return g == 0 ? 1.77245385090552f
         : g == 1 ? 0.79266545952121f
         : g == 2 ? 0.59081795030184f
         : g == 3 ? 0.49159027f
         :          0.42988321f;
}

// ---------------- setup: pre-split B matrices to bf16 hi/lo -----------------
__global__ void build_B(const float* __restrict__ sft,
                        const float* __restrict__ isft) {
    const int tid = threadIdx.x;
    for (int i = tid; i < 96 * 48; i += 256) {     // B1[n=p(96)][k(48)]
        int n = i / 48, k = i - n * 48;
        float v = (n < ND && k < NC) ? isft[n * NC + k] : 0.f;
        __nv_bfloat16 hi = __float2bfloat16(v);
        g_B1h[i] = hi;
        g_B1l[i] = __float2bfloat16(v - __bfloat162float(hi));
    }
    for (int i = tid; i < 48 * 96; i += 256) {     // B2[n=k(48)][k=p(96)]
        int n = i / 96, p = i - n * 96;
        float v = (n < NC && p < ND) ? sft[n * ND + p] : 0.f;
        __nv_bfloat16 hi = __float2bfloat16(v);
        g_B2h[i] = hi;
        g_B2l[i] = __float2bfloat16(v - __bfloat162float(hi));
    }
}

// sconv over k in [K0,K0+KN): one thread, one row r; bf16 hi/lo pairs to Y.
// MODE_IN==0: x from smem [k][m] (XSTR). MODE_IN==1: x from gmem [k][b][c].
template <int K0, int KN, int CIN, int XSTR, int MODE_IN>
__device__ __forceinline__ void sconv_seg(const float* __restrict__ xb,
                                          const float* __restrict__ wb,
                                          __nv_bfloat16* __restrict__ yh,
                                          __nv_bfloat16* __restrict__ yl,
                                          int r) {
    constexpr size_t KS = (size_t)NB_TOTAL * CIN;  // gmem k-stride (elems)
    float acc[KN];
#pragma unroll
    for (int kk = 0; kk < KN; kk++) acc[kk] = 0.f;
#pragma unroll 1
    for (int cb = 0; cb < CIN; cb += 4) {
        float wv[4][5];
#pragma unroll
        for (int cc = 0; cc < 4; cc++)
#pragma unroll
            for (int g = 0; g < 5; g++) wv[cc][g] = wb[(cb + cc) * 5 + g];
#pragma unroll
        for (int kk = 0; kk < KN; kk++) {
            float4 xv;
            if constexpr (MODE_IN == 0)
                xv = *reinterpret_cast<const float4*>(xb + (K0 + kk) * XSTR + cb);
            else
                xv = __ldg(reinterpret_cast<const float4*>(
                        xb + (size_t)(K0 + kk) * KS + cb));
            const int g = ggrp(K0 + kk);
            acc[kk] = fmaf(xv.x, wv[0][g], acc[kk]);
            acc[kk] = fmaf(xv.y, wv[1][g], acc[kk]);
            acc[kk] = fmaf(xv.z, wv[2][g], acc[kk]);
            acc[kk] = fmaf(xv.w, wv[3][g], acc[kk]);
        }
    }
#pragma unroll
    for (int kk = 0; kk + 1 < KN; kk += 2) {       // K0 even -> 4B aligned
        const float v0 = acc[kk] * scl_of(K0 + kk);
        const float v1 = acc[kk + 1] * scl_of(K0 + kk + 1);
        const __nv_bfloat16 h0 = __float2bfloat16(v0);
        const __nv_bfloat16 h1 = __float2bfloat16(v1);
        *(uint32_t*)(yh + r * YSTR + K0 + kk) = pack2bf(h0, h1);
        *(uint32_t*)(yl + r * YSTR + K0 + kk) =
            pack2bf(__float2bfloat16(v0 - __bfloat162float(h0)),
                    __float2bfloat16(v1 - __bfloat162float(h1)));
    }
    if constexpr (KN & 1) {
        const int k = K0 + KN - 1;
        const float v = acc[KN - 1] * scl_of(k);
        const __nv_bfloat16 h = __float2bfloat16(v);
        yh[r * YSTR + k] = h;
        yl[r * YSTR + k] = __float2bfloat16(v - __bfloat162float(h));
    }
}

// ---------------- per-layer persistent kernel -------------------------------
template <int CIN, int COUT, int TB, int NW, int MODE_IN, int MODE_OUT>
__global__ void __launch_bounds__(NW * 32, NW == 8 ? 2 : 1)
scnn_layer(const float* __restrict__ in, const float* __restrict__ w,
           float* __restrict__ out, int ntiles) {
    constexpr int M    = NW * 16;
    constexpr int NTT  = NW * 32;
    constexpr int MIN_ = TB * CIN;
    constexpr int XSTR = MIN_ + 4;
    constexpr int WSTR = CIN * 5 + 1;
    constexpr int YSZ  = M * YSTR * 2;
    constexpr int OFF_YL_ = OFF_YH + YSZ;
    constexpr int OFF_X_  = OFF_YH + 2 * YSZ;
    constexpr int XSZ  = (MODE_IN == 0) ? NC * XSTR * 4 : 0;
    constexpr int OFF_W_  = OFF_X_ + XSZ;
    constexpr int MSHIFT  = (NW == 16) ? 8 : 7;
    static_assert(TB * COUT == M, "tile");
    static_assert(CIN % 4 == 0, "c-block");

    extern __shared__ char smc[];
    const uint32_t sb = smem_u32(smc);
    const int tid = threadIdx.x, wid = tid >> 5, lane = tid & 31;

    __nv_bfloat16* Yh = (__nv_bfloat16*)(smc + OFF_YH);
    __nv_bfloat16* Yl = (__nv_bfloat16*)(smc + OFF_YL_);
    float* s_x = (float*)(smc + OFF_X_);
    float* s_w = (float*)(smc + OFF_W_);

    // ---- one-time setup: zero Y (pads), copy B tiles, load W ---------------
    for (int i = tid; i < 2 * YSZ / 4; i += NTT)
        ((uint32_t*)(smc + OFF_YH))[i] = 0;
    {
        const uint32_t* s1h = (const uint32_t*)g_B1h;
        const uint32_t* s1l = (const uint32_t*)g_B1l;
        uint32_t* d1h = (uint32_t*)(smc + OFF_B1H);
        uint32_t* d1l = (uint32_t*)(smc + OFF_B1L);
        for (int i = tid; i < 96 * 24; i += NTT) {
            int n = i / 24, kk = i - n * 24;
            d1h[(n * B1STR) / 2 + kk] = s1h[i];
            d1l[(n * B1STR) / 2 + kk] = s1l[i];
        }
        const uint32_t* s2h = (const uint32_t*)g_B2h;
        const uint32_t* s2l = (const uint32_t*)g_B2l;
        uint32_t* d2h = (uint32_t*)(smc + OFF_B2H);
        uint32_t* d2l = (uint32_t*)(smc + OFF_B2L);
        for (int i = tid; i < 48 * 48; i += NTT) {
            int n = i / 48, kk = i - n * 48;
            d2h[(n * B2STR) / 2 + kk] = s2h[i];
            d2l[(n * B2STR) / 2 + kk] = s2l[i];
        }
    }
    for (int i = tid; i < COUT * CIN * 5; i += NTT) {
        int o = i / (CIN * 5);
        s_w[o * WSTR + (i - o * (CIN * 5))] = w[i];
    }

    // ---- loop-invariant addresses ------------------------------------------
    const int m0 = wid * 16;
    const int g = lane >> 3, rr = lane & 7;
    const uint32_t aY  = sb + OFF_YH +
        ((m0 + (g & 1) * 8 + rr) * YSTR + (g >> 1) * 8) * 2;
    const uint32_t bB1 = sb + OFF_B1H +
        (((g >> 1) * 8 + rr) * B1STR + (g & 1) * 8) * 2;
    const uint32_t bB2 = sb + OFF_B2H +
        (((g >> 1) * 8 + rr) * B2STR + (g & 1) * 8) * 2;
    const int qr = lane >> 2, qc = lane & 3;

    // sconv mapping
    const int rS = tid & (M - 1);
    const int segS = tid >> MSHIFT;            // 0 or 1 (warp-uniform)
    const int tS = rS / COUT, oS = rS % COUT;
    const float* wbS = s_w + oS * WSTR;

    // ---- L1 only: stage first tile's x -------------------------------------
    int t = blockIdx.x;
    if constexpr (MODE_IN == 0) {
        if (t < ntiles) {
            const size_t bi = (size_t)t * (MIN_ * NC);
            for (int i = tid; i < MIN_ * NC; i += NTT) {
                int m = i / NC, k = i - m * NC;
                s_x[k * XSTR + m] = in[bi + i];
            }
        }
    }
    __syncthreads();

    // ---- persistent tile loop ----------------------------------------------
    for (; t < ntiles; t += gridDim.x) {
        // phase A: sconv -> Y
        {
            const float* xb;
            if constexpr (MODE_IN == 0) {
                xb = s_x + tS * CIN;
            } else {
                int b = t * TB + tS;
                if (b >= NB_TOTAL) b = NB_TOTAL - 1;   // clamp (guarded store)
                xb = in + (size_t)b * CIN;
            }
            if (segS == 0)
                sconv_seg< 0, 22, CIN, XSTR, MODE_IN>(xb, wbS, Yh, Yl, rS);
            else
                sconv_seg<22, 23, CIN, XSTR, MODE_IN>(xb, wbS, Yh, Yl, rS);
        }
        __syncthreads();

        // phase B: GEMM1 (full N=96 per warp) -> register relu/split -> GEMM2
        float c1[12][4];
#pragma unroll
        for (int i = 0; i < 12; i++)
#pragma unroll
            for (int j = 0; j < 4; j++) c1[i][j] = 0.f;

#pragma unroll
        for (int ks = 0; ks < 3; ks++) {
            uint32_t ah[4], al[4];
            ldsm_x4(ah, aY + ks * 32);
            ldsm_x4(al, aY + ks * 32 + YSZ);
#pragma unroll
            for (int np = 0; np < 6; np++) {
                const uint32_t bo = bB1 + ks * 32 + np * (16 * B1STR * 2);
                uint32_t bh[4], bl[4];
                ldsm_x4(bh, bo);
                ldsm_x4(bl, bo + DB1);
                mma_bf16(c1[2 * np], ah, bh[0], bh[1]);
                mma_bf16(c1[2 * np], ah, bl[0], bl[1]);
                mma_bf16(c1[2 * np], al, bh[0], bh[1]);
                mma_bf16(c1[2 * np + 1], ah, bh[2], bh[3]);
                mma_bf16(c1[2 * np + 1], ah, bl[2], bl[3]);
                mma_bf16(c1[2 * np + 1], al, bh[2], bh[3]);
            }
        }

        // L1 only: overlap next tile's x staging (x dead after sconv)
        if constexpr (MODE_IN == 0) {
            const int tn = t + gridDim.x;
            if (tn < ntiles) {
                const size_t bi = (size_t)tn * (MIN_ * NC);
                for (int i = tid; i < MIN_ * NC; i += NTT) {
                    int m = i / NC, k = i - m * NC;
                    s_x[k * XSTR + m] = in[bi + i];
                }
            }
        }

        float c2[6][4];
#pragma unroll
        for (int i = 0; i < 6; i++)
#pragma unroll
            for (int j = 0; j < 4; j++) c2[i][j] = 0.f;

#pragma unroll
        for (int kc = 0; kc < 6; kc++) {
            // repack: sig fragment (relu + hi/lo split) from c1, in registers
            uint32_t a2h[4], a2l[4];
#pragma unroll
            for (int u = 0; u < 2; u++)
#pragma unroll
                for (int v = 0; v < 2; v++) {
                    const float p0 = fmaxf(c1[2 * kc + u][2 * v], 0.f);
                    const float p1 = fmaxf(c1[2 * kc + u][2 * v + 1], 0.f);
                    const __nv_bfloat16 h0 = __float2bfloat16(p0);
                    const __nv_bfloat16 h1 = __float2bfloat16(p1);
                    a2h[2 * u + v] = pack2bf(h0, h1);
                    a2l[2 * u + v] =
                        pack2bf(__float2bfloat16(p0 - __bfloat162float(h0)),
                                __float2bfloat16(p1 - __bfloat162float(h1)));
                }
#pragma unroll
            for (int np = 0; np < 3; np++) {
                const uint32_t bo = bB2 + kc * 32 + np * (16 * B2STR * 2);
                uint32_t bh[4], bl[4];
                ldsm_x4(bh, bo);
                ldsm_x4(bl, bo + DB2);
                mma_bf16(c2[2 * np], a2h, bh[0], bh[1]);
                mma_bf16(c2[2 * np], a2h, bl[0], bl[1]);
                mma_bf16(c2[2 * np], a2l, bh[0], bh[1]);
                mma_bf16(c2[2 * np + 1], a2h, bh[2], bh[3]);
                mma_bf16(c2[2 * np + 1], a2h, bl[2], bl[3]);
                mma_bf16(c2[2 * np + 1], a2l, bh[2], bh[3]);
            }
        }

        // store c2 straight to gmem
        if constexpr (MODE_OUT == 1) {           // [k][b][ch] layout
            const int tb0 = t * TB;
#pragma unroll
            for (int j2 = 0; j2 < 6; j2++) {
                const int col0 = j2 * 8 + 2 * qc;
#pragma unroll
                for (int half = 0; half < 2; half++) {
                    const int m = m0 + qr + 8 * half;
                    const int b = tb0 + m / COUT;
                    const int ch = m % COUT;
                    if (b < NB_TOTAL) {
                        if (col0 < NC)
                            out[((size_t)col0 * NB_TOTAL + b) * COUT + ch] =
                                c2[j2][2 * half];
                        if (col0 + 1 < NC)
                            out[((size_t)(col0 + 1) * NB_TOTAL + b) * COUT + ch] =
                                c2[j2][2 * half + 1];
                    }
                }
            }
        } else {                                 // standard [b][ch][k] (L6)
#pragma unroll
            for (int j2 = 0; j2 < 6; j2++) {
                const int col0 = j2 * 8 + 2 * qc;
#pragma unroll
                for (int half = 0; half < 2; half++) {
                    const int m = m0 + qr + 8 * half;
                    if (t * TB + m / COUT < NB_TOTAL) {
                        const size_t ro = ((size_t)t * M + m) * NC;
                        if (col0 < NC)     out[ro + col0]     = c2[j2][2 * half];
                        if (col0 + 1 < NC) out[ro + col0 + 1] = c2[j2][2 * half + 1];
                    }
                }
            }
        }
        __syncthreads();   // protect Y (and L1's s_x) before next sconv
    }
}

// ---------------- host ------------------------------------------------------
extern "C" void kernel_launch(void* const* d_in, const int* in_sizes, int n_in,
                              void* d_out, int out_size) {
    (void)in_sizes; (void)n_in; (void)out_size;

    const float* x    = (const float*)d_in[0];
    const float* sft  = (const float*)d_in[1];
    const float* isft = (const float*)d_in[2];
    const float* w1   = (const float*)d_in[3];
    const float* w2   = (const float*)d_in[4];
    const float* w3   = (const float*)d_in[5];
    const float* w4   = (const float*)d_in[6];
    const float* w5   = (const float*)d_in[7];
    const float* w6   = (const float*)d_in[8];
    float* out = (float*)d_out;

    float *bufA = nullptr, *bufB = nullptr;
    cudaGetSymbolAddress((void**)&bufA, g_bufA);
    cudaGetSymbolAddress((void**)&bufB, g_bufB);

    cudaFuncSetAttribute((const void*)scnn_layer<4, 16, 16, 16, 0, 1>,
        cudaFuncAttributeMaxDynamicSharedMemorySize, smem_total_c(4, 16, 16, 16, 0));
    cudaFuncSetAttribute((const void*)scnn_layer<16, 32, 8, 16, 1, 1>,
        cudaFuncAttributeMaxDynamicSharedMemorySize, smem_total_c(16, 32, 8, 16, 1));
    cudaFuncSetAttribute((const void*)scnn_layer<32, 64, 4, 16, 1, 1>,
        cudaFuncAttributeMaxDynamicSharedMemorySize, smem_total_c(32, 64, 4, 16, 1));
    cudaFuncSetAttribute((const void*)scnn_layer<64, 32, 4, 8, 1, 1>,
        cudaFuncAttributeMaxDynamicSharedMemorySize, smem_total_c(64, 32, 4, 8, 1));
    cudaFuncSetAttribute((const void*)scnn_layer<32, 16, 8, 8, 1, 1>,
        cudaFuncAttributeMaxDynamicSharedMemorySize, smem_total_c(32, 16, 8, 8, 1));
    cudaFuncSetAttribute((const void*)scnn_layer<16, 4, 32, 8, 1, 0>,
        cudaFuncAttributeMaxDynamicSharedMemorySize, smem_total_c(16, 4, 32, 8, 0) -
            NC * (32 * 16 + 4) * 4);   // MODE_IN=1: no X region

    build_B<<<1, 256>>>(sft, isft);

    // L1: in [b][c][k] via smem stage; out kbc. M=256, 16 warps.
    scnn_layer<4, 16, 16, 16, 0, 1><<<148, 512,
        smem_total_c(4, 16, 16, 16, 0)>>>(x, w1, bufA, 3125);
    // L2-L5: kbc -> kbc
    scnn_layer<16, 32, 8, 16, 1, 1><<<148, 512,
        smem_total_c(16, 32, 8, 16, 1)>>>(bufA, w2, bufB, 6250);
    scnn_layer<32, 64, 4, 16, 1, 1><<<148, 512,
        smem_total_c(32, 64, 4, 16, 1)>>>(bufB, w3, bufA, 12500);
    scnn_layer<64, 32, 4, 8, 1, 1><<<296, 256,
        smem_total_c(64, 32, 4, 8, 1)>>>(bufA, w4, bufB, 12500);
    scnn_layer<32, 16, 8, 8, 1, 1><<<296, 256,
        smem_total_c(32, 16, 8, 8, 1)>>>(bufB, w5, bufA, 6250);
    // L6: kbc -> standard [b][ch][k] into d_out (tail tile guarded)
    scnn_layer<16, 4, 32, 8, 1, 0><<<296, 256,
        smem_total_c(16, 4, 32, 8, 1)>>>(bufA, w6, out, 1563);
}